// round 7
// baseline (speedup 1.0000x reference)
#include <cuda_runtime.h>

#define BINS  10
#define ROWW  11            // float2 per thread row: 10 bins + 1 pad (also kills bank conflicts)
#define BLOCK 256
#define OCC   4
#define GRID  (148 * OCC)

// Global scratch (zero at module load; reset by last block each run -> graph-replayable).
__device__ float    g_sum[BINS];
__device__ float    g_cnt[BINS];
__device__ unsigned g_ticket;

__device__ __forceinline__ void ghm_elem(float xx, int tt, float2* __restrict__ row) {
    // z = x if t==0 else -x  (sign-bit xor). Then g = sigmoid(z), ce = softplus(z).
    const int   zi = __float_as_int(xx) ^ (tt << 31);
    const float z  = __int_as_float(zi);
    const float a  = __expf(-fabsf(z));          // MUFU.EX2
    const float p  = 1.0f + a;
    const float r  = __fdividef(1.0f, p);        // MUFU.RCP  (= sigmoid(|z|))
    const float g  = (zi >= 0) ? r : (1.0f - r); // sigmoid(z) = |sigmoid(x)-t|
    // ce = max(z,0) + log1p(a) = max(z,0) + ln2*log2(1+a)
    const float ce = fmaxf(z, 0.0f) + 0.69314718055994531f * __log2f(p); // MUFU.LG2
    const int bin  = (int)(g * 9.9999f);         // g < 1 strictly -> bin in [0,9]
    float2 v = row[bin];                         // LDS.64
    v.x += ce;
    v.y += 1.0f;
    row[bin] = v;                                // STS.64
}

__global__ void __launch_bounds__(BLOCK, OCC)
ghm_fused(const float* __restrict__ x, const int* __restrict__ tg, int n,
          float* __restrict__ out, int out_size) {
    __shared__ float2 rows[BLOCK][ROWW];
    __shared__ float  sh_fin[2 * BINS];
    __shared__ bool   s_last;

    const int tid = threadIdx.x;
    float2* __restrict__ row = rows[tid];
    #pragma unroll
    for (int b = 0; b < ROWW; ++b) row[b] = make_float2(0.0f, 0.0f);

    const int n4      = n >> 2;
    const int stride4 = GRID * BLOCK;
    const int idx     = blockIdx.x * BLOCK + tid;
    const int per_it  = 4 * stride4;          // float4-groups per super-iteration
    const int full    = n4 / per_it;          // fully-valid super-iterations (uniform)
    const float4* __restrict__ x4 = (const float4*)x;
    const int4*   __restrict__ t4 = (const int4*)tg;

    // Hot loop: 16 elems/thread/iter, 8 front-batched LDG.128, zero validity logic.
    for (int it = 0; it < full; ++it) {
        const int base = idx + it * per_it;
        float4 xv[4]; int4 tv[4];
        #pragma unroll
        for (int k = 0; k < 4; ++k) {
            xv[k] = x4[base + k * stride4];
            tv[k] = t4[base + k * stride4];
        }
        #pragma unroll
        for (int k = 0; k < 4; ++k) {
            ghm_elem(xv[k].x, tv[k].x, row);
            ghm_elem(xv[k].y, tv[k].y, row);
            ghm_elem(xv[k].z, tv[k].z, row);
            ghm_elem(xv[k].w, tv[k].w, row);
        }
    }

    // Ragged float4 tail (no warp collectives in flight -> divergence is fine).
    for (int i = idx + full * per_it; i < n4; i += stride4) {
        const float4 xv = x4[i];
        const int4   tv = t4[i];
        ghm_elem(xv.x, tv.x, row);
        ghm_elem(xv.y, tv.y, row);
        ghm_elem(xv.z, tv.z, row);
        ghm_elem(xv.w, tv.w, row);
    }

    // Scalar tail (n % 4), block 0 only.
    if (blockIdx.x == 0 && tid < (n & 3)) {
        const int i = (n & ~3) + tid;
        ghm_elem(x[i], tg[i], row);
    }

    // ── Reduction: own smem row -> regs -> warp butterfly -> block -> global ──
    float sums[BINS], cnts[BINS];
    #pragma unroll
    for (int b = 0; b < BINS; ++b) {
        const float2 v = row[b];
        sums[b] = v.x; cnts[b] = v.y;
    }
    #pragma unroll
    for (int b = 0; b < BINS; ++b) {
        #pragma unroll
        for (int o = 16; o; o >>= 1) {
            sums[b] += __shfl_xor_sync(0xffffffffu, sums[b], o);
            cnts[b] += __shfl_xor_sync(0xffffffffu, cnts[b], o);
        }
    }
    if (tid < 2 * BINS) sh_fin[tid] = 0.0f;
    __syncthreads();
    if ((tid & 31) == 0) {
        #pragma unroll
        for (int b = 0; b < BINS; ++b) {
            atomicAdd(&sh_fin[b], sums[b]);
            atomicAdd(&sh_fin[BINS + b], cnts[b]);
        }
    }
    __syncthreads();
    if (tid < BINS) {
        atomicAdd(&g_sum[tid], sh_fin[tid]);
        atomicAdd(&g_cnt[tid], sh_fin[BINS + tid]);
    }

    // Last-block ticket: finalize + reset scratch for next graph replay.
    __threadfence();
    if (tid == 0) {
        const unsigned t = atomicAdd(&g_ticket, 1u);
        s_last = (t == (unsigned)(GRID - 1));
    }
    __syncthreads();
    if (s_last && tid < 32) {
        float c = 0.0f, ssum = 0.0f;
        if (tid < BINS) {
            c    = atomicAdd(&g_cnt[tid], 0.0f);   // coherent L2 read
            ssum = atomicAdd(&g_sum[tid], 0.0f);
        }
        const unsigned ne = __ballot_sync(0xffffffffu, (tid < BINS) && (c > 0.0f));
        const float nonempty = (float)__popc(ne);
        float term = 0.0f;
        if (tid < BINS)
            term = ssum / fmaxf(c * nonempty, 1e-6f);  // mean(ce*w) = sum_b S_b/gd_b
        #pragma unroll
        for (int o = 16; o; o >>= 1)
            term += __shfl_xor_sync(0xffffffffu, term, o);
        for (int i = tid; i < out_size; i += 32) out[i] = term;
        if (tid < BINS) { g_sum[tid] = 0.0f; g_cnt[tid] = 0.0f; }
        if (tid == 0) g_ticket = 0u;
    }
}

extern "C" void kernel_launch(void* const* d_in, const int* in_sizes, int n_in,
                              void* d_out, int out_size) {
    const float* x = (const float*)d_in[0];
    const int*   t = (const int*)d_in[1];
    const int n = in_sizes[0];
    ghm_fused<<<GRID, BLOCK>>>(x, t, n, (float*)d_out, out_size);
}

// round 8
// speedup vs baseline: 1.7805x; 1.7805x over previous
#include <cuda_runtime.h>

#define BINS  10
#define BLOCK 256
#define OCC   4
#define GRID  (148 * OCC)

// Global scratch (zero at module load; reset by last block each run -> graph-replayable).
__device__ float    g_sum[BINS];
__device__ float    g_cnt[BINS];
__device__ unsigned g_ticket;

// Bin-edge thresholds in z-space: T_k = logit(k/9.9999).
// Symmetric set on |z| (negative-side edges differ by <4e-5 in z; impact ~1e-5 rel).
#define T5  2.0e-5f
#define U0  0.4054901f
#define U1  0.8473313f
#define U2  1.3863444f
#define U3  2.1973246f

// rowbase = (char*)rows + tid*8 ; cell for bin b at rowbase + b*2048 (conflict-free).
__device__ __forceinline__ void ghm_elem(float xx, int tt, char* __restrict__ rowbase) {
    // z = x if t==0 else -x (sign-bit xor). Then g = sigmoid(z), ce = softplus(z).
    const int   zi = __float_as_int(xx) ^ (tt << 31);
    const float z  = __int_as_float(zi);
    const float u  = fabsf(z);
    const float a  = __expf(-u);                 // MUFU.EX2
    // ce = max(z,0) + log1p(a) = max(z,0) + ln2*log2(1+a)
    const float ce = fmaxf(z, 0.0f)
                   + 0.69314718055994531f * __log2f(1.0f + a);  // MUFU.LG2
    // bin via z-space thresholds (no RCP): monotone in z.
    int m = 0;
    m += (u >= U0);
    m += (u >= U1);
    m += (u >= U2);
    m += (u >= U3);
    const int bin = (z >= T5) ? (5 + m) : (4 - m);
    float2* cell = (float2*)(rowbase + (bin << 11));            // IMAD addr
    float2 v = *cell;                                           // LDS.64 (conflict-free)
    v.x += ce;
    v.y += 1.0f;
    *cell = v;                                                  // STS.64 (conflict-free)
}

__global__ void __launch_bounds__(BLOCK, OCC)
ghm_fused(const float* __restrict__ x, const int* __restrict__ tg, int n,
          float* __restrict__ out, int out_size) {
    __shared__ float2 rows[BINS][BLOCK];   // [bin][tid] -> bank = tid, bin moves whole rows
    __shared__ float  sh_fin[2 * BINS];
    __shared__ bool   s_last;

    const int tid = threadIdx.x;
    char* __restrict__ rowbase = (char*)rows + tid * (int)sizeof(float2);
    #pragma unroll
    for (int b = 0; b < BINS; ++b) rows[b][tid] = make_float2(0.0f, 0.0f);

    const int n4      = n >> 2;
    const int stride4 = GRID * BLOCK;
    const int idx     = blockIdx.x * BLOCK + tid;
    const int per_it  = 4 * stride4;          // float4-groups per super-iteration
    const int full    = n4 / per_it;          // fully-valid super-iterations (uniform)
    const float4* __restrict__ x4 = (const float4*)x;
    const int4*   __restrict__ t4 = (const int4*)tg;

    // Hot loop: 16 elems/thread/iter, 8 front-batched LDG.128, zero validity logic.
    for (int it = 0; it < full; ++it) {
        const int base = idx + it * per_it;
        float4 xv[4]; int4 tv[4];
        #pragma unroll
        for (int k = 0; k < 4; ++k) {
            xv[k] = x4[base + k * stride4];
            tv[k] = t4[base + k * stride4];
        }
        #pragma unroll
        for (int k = 0; k < 4; ++k) {
            ghm_elem(xv[k].x, tv[k].x, rowbase);
            ghm_elem(xv[k].y, tv[k].y, rowbase);
            ghm_elem(xv[k].z, tv[k].z, rowbase);
            ghm_elem(xv[k].w, tv[k].w, rowbase);
        }
    }

    // Ragged float4 tail (no warp collectives in flight -> divergence is fine).
    for (int i = idx + full * per_it; i < n4; i += stride4) {
        const float4 xv = x4[i];
        const int4   tv = t4[i];
        ghm_elem(xv.x, tv.x, rowbase);
        ghm_elem(xv.y, tv.y, rowbase);
        ghm_elem(xv.z, tv.z, rowbase);
        ghm_elem(xv.w, tv.w, rowbase);
    }

    // Scalar tail (n % 4), block 0 only.
    if (blockIdx.x == 0 && tid < (n & 3)) {
        const int i = (n & ~3) + tid;
        ghm_elem(x[i], tg[i], rowbase);
    }

    // ── Reduction: own smem column -> regs -> warp butterfly -> block -> global ──
    float sums[BINS], cnts[BINS];
    #pragma unroll
    for (int b = 0; b < BINS; ++b) {
        const float2 v = rows[b][tid];     // own cells only; no sync needed
        sums[b] = v.x; cnts[b] = v.y;
    }
    #pragma unroll
    for (int b = 0; b < BINS; ++b) {
        #pragma unroll
        for (int o = 16; o; o >>= 1) {
            sums[b] += __shfl_xor_sync(0xffffffffu, sums[b], o);
            cnts[b] += __shfl_xor_sync(0xffffffffu, cnts[b], o);
        }
    }
    if (tid < 2 * BINS) sh_fin[tid] = 0.0f;
    __syncthreads();
    if ((tid & 31) == 0) {
        #pragma unroll
        for (int b = 0; b < BINS; ++b) {
            atomicAdd(&sh_fin[b], sums[b]);
            atomicAdd(&sh_fin[BINS + b], cnts[b]);
        }
    }
    __syncthreads();
    if (tid < BINS) {
        atomicAdd(&g_sum[tid], sh_fin[tid]);
        atomicAdd(&g_cnt[tid], sh_fin[BINS + tid]);
    }

    // Last-block ticket: finalize + reset scratch for next graph replay.
    __threadfence();
    if (tid == 0) {
        const unsigned t = atomicAdd(&g_ticket, 1u);
        s_last = (t == (unsigned)(GRID - 1));
    }
    __syncthreads();
    if (s_last && tid < 32) {
        float c = 0.0f, ssum = 0.0f;
        if (tid < BINS) {
            c    = atomicAdd(&g_cnt[tid], 0.0f);   // coherent L2 read
            ssum = atomicAdd(&g_sum[tid], 0.0f);
        }
        const unsigned ne = __ballot_sync(0xffffffffu, (tid < BINS) && (c > 0.0f));
        const float nonempty = (float)__popc(ne);
        float term = 0.0f;
        if (tid < BINS)
            term = ssum / fmaxf(c * nonempty, 1e-6f);  // mean(ce*w) = sum_b S_b/gd_b
        #pragma unroll
        for (int o = 16; o; o >>= 1)
            term += __shfl_xor_sync(0xffffffffu, term, o);
        for (int i = tid; i < out_size; i += 32) out[i] = term;
        if (tid < BINS) { g_sum[tid] = 0.0f; g_cnt[tid] = 0.0f; }
        if (tid == 0) g_ticket = 0u;
    }
}

extern "C" void kernel_launch(void* const* d_in, const int* in_sizes, int n_in,
                              void* d_out, int out_size) {
    const float* x = (const float*)d_in[0];
    const int*   t = (const int*)d_in[1];
    const int n = in_sizes[0];
    ghm_fused<<<GRID, BLOCK>>>(x, t, n, (float*)d_out, out_size);
}

// round 9
// speedup vs baseline: 1.7823x; 1.0010x over previous
#include <cuda_runtime.h>

#define BINS  10
#define BLOCK 256
#define OCC   4
#define GRID  (148 * OCC)

// Global scratch (zero at module load; reset by last block each run -> graph-replayable).
__device__ float    g_sum[BINS];
__device__ float    g_cnt[BINS];
__device__ unsigned g_ticket;

#define LOG2E 1.4426950408889634f
#define LN2   0.69314718055994531f

// rowbase = (char*)rows + tid*8 ; cell for bin b at rowbase + b*2048 (conflict-free:
// bank-pair = tid mod 16, bin term moves whole 32-bank rows).
__device__ __forceinline__ void ghm_elem(float xx, int tt, char* __restrict__ rowbase) {
    // z = x if t==0 else -x. Adding t<<31 flips only the sign bit (lower bits add 0) -> 1 LEA.
    const int   zi = __float_as_int(xx) + (int)(((unsigned)tt) << 31);
    const float z  = __int_as_float(zi);
    const float a  = exp2f(z * LOG2E);            // e^z        (FMUL + MUFU.EX2)
    const float p  = 1.0f + a;                    // 1 + e^z    (inf-safe)
    const float l  = __log2f(p);                  // MUFU.LG2: ce = ln2 * l (scaled at finalize)
    const float r  = __frcp_rn(p);                // MUFU.RCP: sigmoid(z) = 1 - r
    const float g9 = 9.9999f - 9.9999f * r;       // FFMA: g * (BINS - 1e-4), in [0, 9.9999)
    const int  bin = (int)g9;                     // F2I trunc; p=inf -> r=0 -> bin 9
    float2* cell = (float2*)(rowbase + (bin << 11));
    float2 v = *cell;                             // LDS.64
    v.x += l;
    v.y += 1.0f;
    *cell = v;                                    // STS.64
}

__global__ void __launch_bounds__(BLOCK, OCC)
ghm_fused(const float* __restrict__ x, const int* __restrict__ tg, int n,
          float* __restrict__ out, int out_size) {
    __shared__ float2 rows[BINS][BLOCK];   // [bin][tid]
    __shared__ float  sh_fin[2 * BINS];
    __shared__ bool   s_last;

    const int tid = threadIdx.x;
    char* __restrict__ rowbase = (char*)rows + tid * (int)sizeof(float2);
    #pragma unroll
    for (int b = 0; b < BINS; ++b) rows[b][tid] = make_float2(0.0f, 0.0f);

    const int n4      = n >> 2;
    const int stride4 = GRID * BLOCK;
    const int idx     = blockIdx.x * BLOCK + tid;
    const int per_it  = 4 * stride4;          // float4-groups per super-iteration
    const int full    = n4 / per_it;          // fully-valid super-iterations (uniform)
    const float4* __restrict__ x4 = (const float4*)x;
    const int4*   __restrict__ t4 = (const int4*)tg;

    // Hot loop: 16 elems/thread/iter, 8 front-batched LDG.128, zero validity logic.
    for (int it = 0; it < full; ++it) {
        const int base = idx + it * per_it;
        float4 xv[4]; int4 tv[4];
        #pragma unroll
        for (int k = 0; k < 4; ++k) {
            xv[k] = x4[base + k * stride4];
            tv[k] = t4[base + k * stride4];
        }
        #pragma unroll
        for (int k = 0; k < 4; ++k) {
            ghm_elem(xv[k].x, tv[k].x, rowbase);
            ghm_elem(xv[k].y, tv[k].y, rowbase);
            ghm_elem(xv[k].z, tv[k].z, rowbase);
            ghm_elem(xv[k].w, tv[k].w, rowbase);
        }
    }

    // Ragged float4 tail.
    for (int i = idx + full * per_it; i < n4; i += stride4) {
        const float4 xv = x4[i];
        const int4   tv = t4[i];
        ghm_elem(xv.x, tv.x, rowbase);
        ghm_elem(xv.y, tv.y, rowbase);
        ghm_elem(xv.z, tv.z, rowbase);
        ghm_elem(xv.w, tv.w, rowbase);
    }

    // Scalar tail (n % 4), block 0 only.
    if (blockIdx.x == 0 && tid < (n & 3)) {
        const int i = (n & ~3) + tid;
        ghm_elem(x[i], tg[i], rowbase);
    }

    // ── Reduction: own smem column -> regs -> warp butterfly -> block -> global ──
    float sums[BINS], cnts[BINS];
    #pragma unroll
    for (int b = 0; b < BINS; ++b) {
        const float2 v = rows[b][tid];     // own cells only; no sync needed
        sums[b] = v.x; cnts[b] = v.y;
    }
    #pragma unroll
    for (int b = 0; b < BINS; ++b) {
        #pragma unroll
        for (int o = 16; o; o >>= 1) {
            sums[b] += __shfl_xor_sync(0xffffffffu, sums[b], o);
            cnts[b] += __shfl_xor_sync(0xffffffffu, cnts[b], o);
        }
    }
    if (tid < 2 * BINS) sh_fin[tid] = 0.0f;
    __syncthreads();
    if ((tid & 31) == 0) {
        #pragma unroll
        for (int b = 0; b < BINS; ++b) {
            atomicAdd(&sh_fin[b], sums[b]);
            atomicAdd(&sh_fin[BINS + b], cnts[b]);
        }
    }
    __syncthreads();
    if (tid < BINS) {
        atomicAdd(&g_sum[tid], sh_fin[tid]);
        atomicAdd(&g_cnt[tid], sh_fin[BINS + tid]);
    }

    // Last-block ticket: finalize + reset scratch for next graph replay.
    __threadfence();
    if (tid == 0) {
        const unsigned t = atomicAdd(&g_ticket, 1u);
        s_last = (t == (unsigned)(GRID - 1));
    }
    __syncthreads();
    if (s_last && tid < 32) {
        float c = 0.0f, ssum = 0.0f;
        if (tid < BINS) {
            c    = atomicAdd(&g_cnt[tid], 0.0f);   // coherent L2 read
            ssum = atomicAdd(&g_sum[tid], 0.0f);
        }
        const unsigned ne = __ballot_sync(0xffffffffu, (tid < BINS) && (c > 0.0f));
        const float nonempty = (float)__popc(ne);
        float term = 0.0f;
        if (tid < BINS)
            term = (LN2 * ssum) / fmaxf(c * nonempty, 1e-6f);  // deferred ln2 scale
        #pragma unroll
        for (int o = 16; o; o >>= 1)
            term += __shfl_xor_sync(0xffffffffu, term, o);
        for (int i = tid; i < out_size; i += 32) out[i] = term;
        if (tid < BINS) { g_sum[tid] = 0.0f; g_cnt[tid] = 0.0f; }
        if (tid == 0) g_ticket = 0u;
    }
}

extern "C" void kernel_launch(void* const* d_in, const int* in_sizes, int n_in,
                              void* d_out, int out_size) {
    const float* x = (const float*)d_in[0];
    const int*   t = (const int*)d_in[1];
    const int n = in_sizes[0];
    ghm_fused<<<GRID, BLOCK>>>(x, t, n, (float*)d_out, out_size);
}